// round 13
// baseline (speedup 1.0000x reference)
#include <cuda_runtime.h>
#include <cuda_bf16.h>

#define N_NODES 50000
#define N_EDGES 800000
#define N_GRAPHS 50
#define IN_FEATS 128
#define H1F 64
#define O2F 32
#define CAP 96     // max in-degree capacity (Poisson(16): P(deg>=96) ~ 0)

// ---------------- scratch (device globals; no allocation allowed) ----------
__device__ __nv_bfloat16 g_z1[N_NODES * H1F];   // bf16: halves agg gather bytes
__device__ float         g_h1[N_NODES * H1F];
__device__ __nv_bfloat16 g_z2[N_NODES * O2F];
__device__ float g_el[N_NODES];
__device__ float g_er[N_NODES];
__device__ int   g_cur[N_NODES];          // degree counter; zero at entry
__device__ int   g_esrc[N_NODES * CAP];   // fixed-capacity adjacency rows
__device__ float g_cnt[N_GRAPHS];

// ---------------- build fixed-capacity adjacency (single kernel) ------------
__global__ void scatter_kernel(const int* __restrict__ src,
                               const int* __restrict__ dst,
                               float* __restrict__ out) {
    if (blockIdx.x == 0) {
        for (int t = threadIdx.x; t < N_GRAPHS * O2F; t += blockDim.x)
            out[t] = 0.0f;
        for (int t = threadIdx.x; t < N_GRAPHS; t += blockDim.x)
            g_cnt[t] = 0.0f;
    }
    int i = blockIdx.x * blockDim.x + threadIdx.x;
    if (i >= N_EDGES / 2) return;
    int j = i + N_EDGES / 2;
    int d0 = dst[i], d1 = dst[j];
    int s0 = src[i], s1 = src[j];
    int p0 = atomicAdd(&g_cur[d0], 1);
    int p1 = atomicAdd(&g_cur[d1], 1);
    if (p0 < CAP) g_esrc[d0 * CAP + p0] = s0;
    if (p1 < CAP) g_esrc[d1 * CAP + p1] = s1;
}

// ---------------- node GEMM + attention logits (NPTx4 register tiling) ------
// fp32 accumulate; el/er from unrounded fp32; Z stored bf16.
template <int IN, int OUT, int NPB, int NPT>
__global__ void gemm_attn_kernel(const float* __restrict__ H,
                                 const float* __restrict__ W,
                                 const float* __restrict__ al,
                                 const float* __restrict__ ar,
                                 __nv_bfloat16* __restrict__ Z,
                                 float* __restrict__ EL,
                                 float* __restrict__ ER) {
    constexpr int CG = OUT / 4;
    constexpr int NG = NPB / NPT;
    constexpr int NT = CG * NG;        // 256
    constexpr int KC = 32;
    constexpr int NKC = IN / KC;
    constexpr int KQ = KC / 4;
    constexpr int PITCH = NPB + 4;

    __shared__ float sx[KC * PITCH];
    __shared__ float sW[KC * OUT];

    int tid = threadIdx.x;
    int base = blockIdx.x * NPB;
    int ng = tid / CG, cg = tid % CG;
    int nn = ng * NPT;

    float4 acc[NPT];
#pragma unroll
    for (int n = 0; n < NPT; n++) acc[n] = make_float4(0.f, 0.f, 0.f, 0.f);

    for (int kc = 0; kc < NKC; kc++) {
        __syncthreads();
        for (int t = tid; t < KC * OUT / 4; t += NT)
            ((float4*)sW)[t] = ((const float4*)W)[kc * (KC * OUT / 4) + t];
        for (int t = tid; t < NPB * KQ; t += NT) {
            int node = t / KQ, kq = t % KQ;
            float4 v = make_float4(0.f, 0.f, 0.f, 0.f);
            if (base + node < N_NODES)
                v = ((const float4*)(H + (size_t)(base + node) * IN))[kc * KQ + kq];
            sx[(kq * 4 + 0) * PITCH + node] = v.x;
            sx[(kq * 4 + 1) * PITCH + node] = v.y;
            sx[(kq * 4 + 2) * PITCH + node] = v.z;
            sx[(kq * 4 + 3) * PITCH + node] = v.w;
        }
        __syncthreads();

#pragma unroll 8
        for (int k = 0; k < KC; k++) {
            float xs[NPT];
#pragma unroll
            for (int q = 0; q < NPT / 4; q++) {
                float4 xq = *(const float4*)(sx + k * PITCH + nn + q * 4);
                xs[q * 4 + 0] = xq.x;
                xs[q * 4 + 1] = xq.y;
                xs[q * 4 + 2] = xq.z;
                xs[q * 4 + 3] = xq.w;
            }
            float4 w = *(const float4*)(sW + k * OUT + cg * 4);
#pragma unroll
            for (int n = 0; n < NPT; n++) {
                acc[n].x += xs[n] * w.x;
                acc[n].y += xs[n] * w.y;
                acc[n].z += xs[n] * w.z;
                acc[n].w += xs[n] * w.w;
            }
        }
    }

    float4 av = ((const float4*)al)[cg];
    float4 rv = ((const float4*)ar)[cg];
#pragma unroll
    for (int n = 0; n < NPT; n++) {
        float l = acc[n].x * av.x + acc[n].y * av.y +
                  acc[n].z * av.z + acc[n].w * av.w;
        float r = acc[n].x * rv.x + acc[n].y * rv.y +
                  acc[n].z * rv.z + acc[n].w * rv.w;
#pragma unroll
        for (int off = CG / 2; off > 0; off >>= 1) {
            l += __shfl_xor_sync(0xffffffffu, l, off);
            r += __shfl_xor_sync(0xffffffffu, r, off);
        }
        int node = base + nn + n;
        if (node < N_NODES) {
            __nv_bfloat162 p0 = __float22bfloat162_rn(make_float2(acc[n].x, acc[n].y));
            __nv_bfloat162 p1 = __float22bfloat162_rn(make_float2(acc[n].z, acc[n].w));
            uint2 packed;
            packed.x = *(unsigned*)&p0;
            packed.y = *(unsigned*)&p1;
            ((uint2*)(Z + (size_t)node * OUT))[cg] = packed;   // 8B per lane
            if (cg == 0) { EL[node] = l; ER[node] = r; }
        }
    }
}

// ---------------- fused softmax + aggregation (max-free), warp per node -----
// bf16 z rows: OUT/8 lanes per edge, each reading 16B (8 values); fp32 accum.
// POOL variant resets g_cur[wid] for the next graph replay.
template <int OUT, bool POOL>
__global__ void node_agg_kernel(const __nv_bfloat16* __restrict__ Z,
                                const float* __restrict__ b,
                                float* __restrict__ Hout,
                                const int* __restrict__ gid,
                                float* __restrict__ out) {
    constexpr int LPE = OUT / 8;       // lanes per edge
    constexpr int EPI = 32 / LPE;      // edges per inner iteration
    int wid  = (blockIdx.x * blockDim.x + threadIdx.x) >> 5;
    int lane = threadIdx.x & 31;
    if (wid >= N_NODES) return;

    int deg = min(g_cur[wid], CAP);
    const int* row = g_esrc + (size_t)wid * CAP;
    float erd = g_er[wid];
    int sub = lane / LPE;
    int fl  = lane % LPE;

    float s_lane = 0.f;
    float acc[8] = {0.f, 0.f, 0.f, 0.f, 0.f, 0.f, 0.f, 0.f};

    for (int base = 0; base < deg; base += 32) {
        int t = base + lane;
        bool valid = t < deg;
        int sN = valid ? row[t] : 0;
        float a = 0.f;
        if (valid) {
            float v = g_el[sN] + erd;
            v = (v > 0.f) ? v : 0.2f * v;
            a = __expf(v);
        }
        s_lane += a;

        int cnt = min(32, deg - base);
        for (int j = 0; j < cnt; j += EPI) {
            int ei = j + sub;
            float alpha = __shfl_sync(0xffffffffu, a, ei);
            int   sn    = __shfl_sync(0xffffffffu, sN, ei);
            uint4 zv = ((const uint4*)(Z + (size_t)sn * OUT))[fl];
            float2 f0 = __bfloat1622float2(*(__nv_bfloat162*)&zv.x);
            float2 f1 = __bfloat1622float2(*(__nv_bfloat162*)&zv.y);
            float2 f2 = __bfloat1622float2(*(__nv_bfloat162*)&zv.z);
            float2 f3 = __bfloat1622float2(*(__nv_bfloat162*)&zv.w);
            acc[0] += alpha * f0.x;  acc[1] += alpha * f0.y;
            acc[2] += alpha * f1.x;  acc[3] += alpha * f1.y;
            acc[4] += alpha * f2.x;  acc[5] += alpha * f2.y;
            acc[6] += alpha * f3.x;  acc[7] += alpha * f3.y;
        }
    }

    float s = s_lane;
#pragma unroll
    for (int off = 16; off > 0; off >>= 1)
        s += __shfl_xor_sync(0xffffffffu, s, off);
#pragma unroll
    for (int off = 16; off >= LPE; off >>= 1)
#pragma unroll
        for (int q = 0; q < 8; q++)
            acc[q] += __shfl_xor_sync(0xffffffffu, acc[q], off);

    if (POOL && lane == 0) g_cur[wid] = 0;   // restore invariant for replay

    if (lane < LPE) {
        float inv_s = (deg > 0) ? 1.f / s : 0.f;
        float4 b0 = ((const float4*)b)[fl * 2];
        float4 b1 = ((const float4*)b)[fl * 2 + 1];
        float h[8];
        h[0] = acc[0] * inv_s + b0.x;  h[1] = acc[1] * inv_s + b0.y;
        h[2] = acc[2] * inv_s + b0.z;  h[3] = acc[3] * inv_s + b0.w;
        h[4] = acc[4] * inv_s + b1.x;  h[5] = acc[5] * inv_s + b1.y;
        h[6] = acc[6] * inv_s + b1.z;  h[7] = acc[7] * inv_s + b1.w;
#pragma unroll
        for (int q = 0; q < 8; q++)
            h[q] = (h[q] > 0.f) ? h[q] : 0.01f * h[q];
        if (POOL) {
            int g = gid[wid];
            float4* dst0 = ((float4*)(out + g * O2F)) + fl * 2;
            atomicAdd(dst0,     make_float4(h[0], h[1], h[2], h[3]));
            atomicAdd(dst0 + 1, make_float4(h[4], h[5], h[6], h[7]));
            if (lane == 0) atomicAdd(&g_cnt[g], 1.f);
        } else {
            float4* dst = ((float4*)(Hout + (size_t)wid * OUT)) + fl * 2;
            dst[0] = make_float4(h[0], h[1], h[2], h[3]);
            dst[1] = make_float4(h[4], h[5], h[6], h[7]);
        }
    }
}

// ---------------- final divide ----------------------------------------------
__global__ void pool_div_kernel(float* __restrict__ out) {
    int i = blockIdx.x * blockDim.x + threadIdx.x;
    if (i >= N_GRAPHS * O2F) return;
    float c = g_cnt[i / O2F];
    out[i] /= fmaxf(c, 1.0f);
}

// ---------------- stream/event singletons (created once, outside capture) ---
static cudaStream_t g_s1;
static cudaEvent_t  g_evFork, g_evJoin;
static int g_res_init = []() {
    cudaStreamCreateWithFlags(&g_s1, cudaStreamNonBlocking);
    cudaEventCreateWithFlags(&g_evFork, cudaEventDisableTiming);
    cudaEventCreateWithFlags(&g_evJoin, cudaEventDisableTiming);
    return 0;
}();

// ---------------- host launch -------------------------------------------------
extern "C" void kernel_launch(void* const* d_in, const int* in_sizes, int n_in,
                              void* d_out, int out_size) {
    const float* x   = (const float*)d_in[0];
    const int*   src = (const int*)d_in[1];
    const int*   dst = (const int*)d_in[2];
    const int*   gid = (const int*)d_in[3];
    const float* W1  = (const float*)d_in[4];
    const float* al1 = (const float*)d_in[5];
    const float* ar1 = (const float*)d_in[6];
    const float* b1  = (const float*)d_in[7];
    const float* W2  = (const float*)d_in[8];
    const float* al2 = (const float*)d_in[9];
    const float* ar2 = (const float*)d_in[10];
    const float* b2  = (const float*)d_in[11];
    float* out = (float*)d_out;

    __nv_bfloat16 *z1, *z2;
    float *h1, *el, *er;
    cudaGetSymbolAddress((void**)&z1, g_z1);
    cudaGetSymbolAddress((void**)&h1, g_h1);
    cudaGetSymbolAddress((void**)&z2, g_z2);
    cudaGetSymbolAddress((void**)&el, g_el);
    cudaGetSymbolAddress((void**)&er, g_er);

    const int TB = 256;
    const int edge2_blocks = (N_EDGES / 2 + TB - 1) / TB;
    const int agg_blocks   = (N_NODES * 32) / TB;        // 6250

    // fork: adjacency build on side stream, gemm1 on main stream
    cudaEventRecord(g_evFork, 0);
    cudaStreamWaitEvent(g_s1, g_evFork, 0);

    scatter_kernel<<<edge2_blocks, TB, 0, g_s1>>>(src, dst, out);
    cudaEventRecord(g_evJoin, g_s1);

    gemm_attn_kernel<IN_FEATS, H1F, 128, 8>
        <<<(N_NODES + 127) / 128, 256>>>(x, W1, al1, ar1, z1, el, er);

    cudaStreamWaitEvent(0, g_evJoin, 0);

    node_agg_kernel<H1F, false><<<agg_blocks, TB>>>(z1, b1, h1, gid, out);

    gemm_attn_kernel<H1F, O2F, 128, 4>
        <<<(N_NODES + 127) / 128, 256>>>(h1, W2, al2, ar2, z2, el, er);

    node_agg_kernel<O2F, true><<<agg_blocks, TB>>>(z2, b2, nullptr, gid, out);

    pool_div_kernel<<<(N_GRAPHS * O2F + TB - 1) / TB, TB>>>(out);
}

// round 14
// speedup vs baseline: 1.0792x; 1.0792x over previous
#include <cuda_runtime.h>

#define N_NODES 50000
#define N_EDGES 800000
#define N_GRAPHS 50
#define IN_FEATS 128
#define H1F 64
#define O2F 32
#define CAP 96     // max in-degree capacity (Poisson(16): P(deg>=96) ~ 0)

// ---------------- scratch (device globals; no allocation allowed) ----------
__device__ float g_z1[N_NODES * H1F];
__device__ float g_h1[N_NODES * H1F];
__device__ float g_z2[N_NODES * O2F];
__device__ float g_el[N_NODES];
__device__ float g_er[N_NODES];
__device__ int   g_cur[N_NODES];          // degree counter; zero at entry
__device__ int   g_esrc[N_NODES * CAP];   // fixed-capacity adjacency rows
__device__ float g_cnt[N_GRAPHS];

// ---------------- build fixed-capacity adjacency (single kernel) ------------
__global__ void scatter_kernel(const int* __restrict__ src,
                               const int* __restrict__ dst,
                               float* __restrict__ out) {
    if (blockIdx.x == 0) {
        for (int t = threadIdx.x; t < N_GRAPHS * O2F; t += blockDim.x)
            out[t] = 0.0f;
        for (int t = threadIdx.x; t < N_GRAPHS; t += blockDim.x)
            g_cnt[t] = 0.0f;
    }
    int i = blockIdx.x * blockDim.x + threadIdx.x;
    if (i >= N_EDGES / 2) return;
    int j = i + N_EDGES / 2;
    int d0 = dst[i], d1 = dst[j];
    int s0 = src[i], s1 = src[j];
    int p0 = atomicAdd(&g_cur[d0], 1);
    int p1 = atomicAdd(&g_cur[d1], 1);
    if (p0 < CAP) g_esrc[d0 * CAP + p0] = s0;
    if (p1 < CAP) g_esrc[d1 * CAP + p1] = s1;
}

// ---------------- node GEMM + attention logits (NPTx4 register tiling) ------
template <int IN, int OUT, int NPB, int NPT>
__global__ void gemm_attn_kernel(const float* __restrict__ H,
                                 const float* __restrict__ W,
                                 const float* __restrict__ al,
                                 const float* __restrict__ ar,
                                 float* __restrict__ Z,
                                 float* __restrict__ EL,
                                 float* __restrict__ ER) {
    constexpr int CG = OUT / 4;
    constexpr int NG = NPB / NPT;
    constexpr int NT = CG * NG;        // 256
    constexpr int KC = 32;
    constexpr int NKC = IN / KC;
    constexpr int KQ = KC / 4;
    constexpr int PITCH = NPB + 4;

    __shared__ float sx[KC * PITCH];
    __shared__ float sW[KC * OUT];

    int tid = threadIdx.x;
    int base = blockIdx.x * NPB;
    int ng = tid / CG, cg = tid % CG;
    int nn = ng * NPT;

    float4 acc[NPT];
#pragma unroll
    for (int n = 0; n < NPT; n++) acc[n] = make_float4(0.f, 0.f, 0.f, 0.f);

    for (int kc = 0; kc < NKC; kc++) {
        __syncthreads();
        for (int t = tid; t < KC * OUT / 4; t += NT)
            ((float4*)sW)[t] = ((const float4*)W)[kc * (KC * OUT / 4) + t];
        for (int t = tid; t < NPB * KQ; t += NT) {
            int node = t / KQ, kq = t % KQ;
            float4 v = make_float4(0.f, 0.f, 0.f, 0.f);
            if (base + node < N_NODES)
                v = ((const float4*)(H + (size_t)(base + node) * IN))[kc * KQ + kq];
            sx[(kq * 4 + 0) * PITCH + node] = v.x;
            sx[(kq * 4 + 1) * PITCH + node] = v.y;
            sx[(kq * 4 + 2) * PITCH + node] = v.z;
            sx[(kq * 4 + 3) * PITCH + node] = v.w;
        }
        __syncthreads();

#pragma unroll 8
        for (int k = 0; k < KC; k++) {
            float xs[NPT];
#pragma unroll
            for (int q = 0; q < NPT / 4; q++) {
                float4 xq = *(const float4*)(sx + k * PITCH + nn + q * 4);
                xs[q * 4 + 0] = xq.x;
                xs[q * 4 + 1] = xq.y;
                xs[q * 4 + 2] = xq.z;
                xs[q * 4 + 3] = xq.w;
            }
            float4 w = *(const float4*)(sW + k * OUT + cg * 4);
#pragma unroll
            for (int n = 0; n < NPT; n++) {
                acc[n].x += xs[n] * w.x;
                acc[n].y += xs[n] * w.y;
                acc[n].z += xs[n] * w.z;
                acc[n].w += xs[n] * w.w;
            }
        }
    }

    float4 av = ((const float4*)al)[cg];
    float4 rv = ((const float4*)ar)[cg];
#pragma unroll
    for (int n = 0; n < NPT; n++) {
        float l = acc[n].x * av.x + acc[n].y * av.y +
                  acc[n].z * av.z + acc[n].w * av.w;
        float r = acc[n].x * rv.x + acc[n].y * rv.y +
                  acc[n].z * rv.z + acc[n].w * rv.w;
#pragma unroll
        for (int off = CG / 2; off > 0; off >>= 1) {
            l += __shfl_xor_sync(0xffffffffu, l, off);
            r += __shfl_xor_sync(0xffffffffu, r, off);
        }
        int node = base + nn + n;
        if (node < N_NODES) {
            ((float4*)(Z + (size_t)node * OUT))[cg] = acc[n];
            if (cg == 0) { EL[node] = l; ER[node] = r; }
        }
    }
}

// ---------------- layer-1 agg: TWO warps per node, split feature halves -----
// Each warp handles 32 of the 64 output features -> EPI=4 (8 inner iterations
// per 32-edge chunk instead of 16). esrc/exp duplicated across the pair
// (same cache lines / MUFU — cheap).
__global__ void node_agg1_kernel(const float* __restrict__ Z,
                                 const float* __restrict__ b,
                                 float* __restrict__ Hout) {
    int gw   = (blockIdx.x * blockDim.x + threadIdx.x) >> 5;
    int wid  = gw >> 1;          // node
    int p    = gw & 1;           // feature-half
    int lane = threadIdx.x & 31;
    if (wid >= N_NODES) return;

    int deg = min(g_cur[wid], CAP);
    const int* row = g_esrc + (size_t)wid * CAP;
    float erd = g_er[wid];
    int sub = lane >> 3;         // 4 edges per iteration
    int fl  = lane & 7;          // quad index within 32 features
    int qoff = p * 8 + fl;       // quad index within the full 64-feature row

    float s_lane = 0.f;
    float4 acc = make_float4(0.f, 0.f, 0.f, 0.f);

    for (int base = 0; base < deg; base += 32) {
        int t = base + lane;
        bool valid = t < deg;
        int sN = valid ? row[t] : 0;
        float a = 0.f;
        if (valid) {
            float v = g_el[sN] + erd;
            v = (v > 0.f) ? v : 0.2f * v;
            a = __expf(v);
        }
        s_lane += a;

        int cnt = min(32, deg - base);
        for (int j = 0; j < cnt; j += 4) {
            int ei = j + sub;
            float alpha = __shfl_sync(0xffffffffu, a, ei);
            int   sn    = __shfl_sync(0xffffffffu, sN, ei);
            float4 zv = ((const float4*)(Z + (size_t)sn * H1F))[qoff];
            acc.x += alpha * zv.x;
            acc.y += alpha * zv.y;
            acc.z += alpha * zv.z;
            acc.w += alpha * zv.w;
        }
    }

    float s = s_lane;
#pragma unroll
    for (int off = 16; off > 0; off >>= 1)
        s += __shfl_xor_sync(0xffffffffu, s, off);
#pragma unroll
    for (int off = 16; off >= 8; off >>= 1) {
        acc.x += __shfl_xor_sync(0xffffffffu, acc.x, off);
        acc.y += __shfl_xor_sync(0xffffffffu, acc.y, off);
        acc.z += __shfl_xor_sync(0xffffffffu, acc.z, off);
        acc.w += __shfl_xor_sync(0xffffffffu, acc.w, off);
    }

    if (lane < 8) {
        float inv_s = (deg > 0) ? 1.f / s : 0.f;
        float4 bq = ((const float4*)b)[qoff];
        float4 h;
        h.x = acc.x * inv_s + bq.x;
        h.y = acc.y * inv_s + bq.y;
        h.z = acc.z * inv_s + bq.z;
        h.w = acc.w * inv_s + bq.w;
        h.x = (h.x > 0.f) ? h.x : 0.01f * h.x;
        h.y = (h.y > 0.f) ? h.y : 0.01f * h.y;
        h.z = (h.z > 0.f) ? h.z : 0.01f * h.z;
        h.w = (h.w > 0.f) ? h.w : 0.01f * h.w;
        ((float4*)(Hout + (size_t)wid * H1F))[qoff] = h;
    }
}

// ---------------- layer-2 agg + pooling (R8-proven form, OUT=32) ------------
// Resets g_cur[wid] for the next graph replay.
__global__ void node_agg2_kernel(const float* __restrict__ Z,
                                 const float* __restrict__ b,
                                 const int* __restrict__ gid,
                                 float* __restrict__ out) {
    constexpr int LPE = O2F / 4;   // 8
    constexpr int EPI = 32 / LPE;  // 4
    int wid  = (blockIdx.x * blockDim.x + threadIdx.x) >> 5;
    int lane = threadIdx.x & 31;
    if (wid >= N_NODES) return;

    int deg = min(g_cur[wid], CAP);
    const int* row = g_esrc + (size_t)wid * CAP;
    float erd = g_er[wid];
    int sub = lane / LPE;
    int fl  = lane % LPE;

    float s_lane = 0.f;
    float4 acc = make_float4(0.f, 0.f, 0.f, 0.f);

    for (int base = 0; base < deg; base += 32) {
        int t = base + lane;
        bool valid = t < deg;
        int sN = valid ? row[t] : 0;
        float a = 0.f;
        if (valid) {
            float v = g_el[sN] + erd;
            v = (v > 0.f) ? v : 0.2f * v;
            a = __expf(v);
        }
        s_lane += a;

        int cnt = min(32, deg - base);
        for (int j = 0; j < cnt; j += EPI) {
            int ei = j + sub;
            float alpha = __shfl_sync(0xffffffffu, a, ei);
            int   sn    = __shfl_sync(0xffffffffu, sN, ei);
            float4 zv = ((const float4*)(Z + (size_t)sn * O2F))[fl];
            acc.x += alpha * zv.x;
            acc.y += alpha * zv.y;
            acc.z += alpha * zv.z;
            acc.w += alpha * zv.w;
        }
    }

    float s = s_lane;
#pragma unroll
    for (int off = 16; off > 0; off >>= 1)
        s += __shfl_xor_sync(0xffffffffu, s, off);
#pragma unroll
    for (int off = 16; off >= LPE; off >>= 1) {
        acc.x += __shfl_xor_sync(0xffffffffu, acc.x, off);
        acc.y += __shfl_xor_sync(0xffffffffu, acc.y, off);
        acc.z += __shfl_xor_sync(0xffffffffu, acc.z, off);
        acc.w += __shfl_xor_sync(0xffffffffu, acc.w, off);
    }

    if (lane == 0) g_cur[wid] = 0;   // restore invariant for replay

    if (lane < LPE) {
        float inv_s = (deg > 0) ? 1.f / s : 0.f;
        float4 bq = ((const float4*)b)[fl];
        float4 h;
        h.x = acc.x * inv_s + bq.x;
        h.y = acc.y * inv_s + bq.y;
        h.z = acc.z * inv_s + bq.z;
        h.w = acc.w * inv_s + bq.w;
        h.x = (h.x > 0.f) ? h.x : 0.01f * h.x;
        h.y = (h.y > 0.f) ? h.y : 0.01f * h.y;
        h.z = (h.z > 0.f) ? h.z : 0.01f * h.z;
        h.w = (h.w > 0.f) ? h.w : 0.01f * h.w;
        int g = gid[wid];
        atomicAdd(((float4*)(out + g * O2F)) + fl, h);
        if (lane == 0) atomicAdd(&g_cnt[g], 1.f);
    }
}

// ---------------- final divide ----------------------------------------------
__global__ void pool_div_kernel(float* __restrict__ out) {
    int i = blockIdx.x * blockDim.x + threadIdx.x;
    if (i >= N_GRAPHS * O2F) return;
    float c = g_cnt[i / O2F];
    out[i] /= fmaxf(c, 1.0f);
}

// ---------------- stream/event singletons (created once, outside capture) ---
static cudaStream_t g_s1;
static cudaEvent_t  g_evFork, g_evJoin;
static int g_res_init = []() {
    cudaStreamCreateWithFlags(&g_s1, cudaStreamNonBlocking);
    cudaEventCreateWithFlags(&g_evFork, cudaEventDisableTiming);
    cudaEventCreateWithFlags(&g_evJoin, cudaEventDisableTiming);
    return 0;
}();

// ---------------- host launch -------------------------------------------------
extern "C" void kernel_launch(void* const* d_in, const int* in_sizes, int n_in,
                              void* d_out, int out_size) {
    const float* x   = (const float*)d_in[0];
    const int*   src = (const int*)d_in[1];
    const int*   dst = (const int*)d_in[2];
    const int*   gid = (const int*)d_in[3];
    const float* W1  = (const float*)d_in[4];
    const float* al1 = (const float*)d_in[5];
    const float* ar1 = (const float*)d_in[6];
    const float* b1  = (const float*)d_in[7];
    const float* W2  = (const float*)d_in[8];
    const float* al2 = (const float*)d_in[9];
    const float* ar2 = (const float*)d_in[10];
    const float* b2  = (const float*)d_in[11];
    float* out = (float*)d_out;

    float *z1, *h1, *z2, *el, *er;
    cudaGetSymbolAddress((void**)&z1, g_z1);
    cudaGetSymbolAddress((void**)&h1, g_h1);
    cudaGetSymbolAddress((void**)&z2, g_z2);
    cudaGetSymbolAddress((void**)&el, g_el);
    cudaGetSymbolAddress((void**)&er, g_er);

    const int TB = 256;
    const int edge2_blocks = (N_EDGES / 2 + TB - 1) / TB;
    const int agg1_blocks  = (N_NODES * 2 * 32) / TB;    // 12500 (2 warps/node)
    const int agg2_blocks  = (N_NODES * 32) / TB;        // 6250

    // fork: adjacency build on side stream, gemm1 on main stream
    cudaEventRecord(g_evFork, 0);
    cudaStreamWaitEvent(g_s1, g_evFork, 0);

    scatter_kernel<<<edge2_blocks, TB, 0, g_s1>>>(src, dst, out);
    cudaEventRecord(g_evJoin, g_s1);

    gemm_attn_kernel<IN_FEATS, H1F, 128, 8>
        <<<(N_NODES + 127) / 128, 256>>>(x, W1, al1, ar1, z1, el, er);

    cudaStreamWaitEvent(0, g_evJoin, 0);

    node_agg1_kernel<<<agg1_blocks, TB>>>(z1, b1, h1);

    gemm_attn_kernel<H1F, O2F, 128, 4>
        <<<(N_NODES + 127) / 128, 256>>>(h1, W2, al2, ar2, z2, el, er);

    node_agg2_kernel<<<agg2_blocks, TB>>>(z2, b2, gid, out);

    pool_div_kernel<<<(N_GRAPHS * O2F + TB - 1) / TB, TB>>>(out);
}